// round 5
// baseline (speedup 1.0000x reference)
#include <cuda_runtime.h>
#include <cuda_bf16.h>

#define GD 128
#define RB 66                         // brick coords 0..65 cover x0 in [-2..128]
#define BRICKS (RB * RB * RB)         // 287,496 bricks per replica
#define TOTAL_BRICKS (8 * BRICKS)     // 8 parity replicas
// Each brick = 2x2x2 cells as bf16 = 16 bytes.
__device__ uint4 g_rep[TOTAL_BRICKS]; // 36.8 MB, zero-initialized at load;
                                      // zero_kernel restores invariant per call.

__device__ __forceinline__ unsigned pack_bf16x2(float lo, float hi) {
    unsigned u;
    asm("cvt.rn.bf16x2.f32 %0, %1, %2;" : "=r"(u) : "f"(hi), "f"(lo));
    return u;
}

__device__ __forceinline__ void red_add_v4_bf16x2(void* addr, unsigned a,
                                                  unsigned b, unsigned c,
                                                  unsigned d) {
    asm volatile("red.global.add.noftz.v4.bf16x2 [%0], {%1, %2, %3, %4};"
                 :: "l"(addr), "r"(a), "r"(b), "r"(c), "r"(d) : "memory");
}

// ---------------------------------------------------------------------------
// One splat = ONE v4.bf16x2 red: replica (x0&1,y0&1,z0&1) makes the 2x2x2
// corner cube one aligned 16B brick. Lane idx = lz*4 + ly*2 + lx.
// ---------------------------------------------------------------------------
__device__ __forceinline__ void splat_one(float cx, float cy, float cz,
                                          float sign) {
    const float x = fmaf(cx, 64.0f, 63.5f);   // ((c+1)*128-1)/2
    const float y = fmaf(cy, 64.0f, 63.5f);
    const float z = fmaf(cz, 64.0f, 63.5f);

    const float x0f = floorf(x), y0f = floorf(y), z0f = floorf(z);
    const float fx = x - x0f, fy = y - y0f, fz = z - z0f;
    int x0 = (int)x0f, y0 = (int)y0f, z0 = (int)z0f;
    // Far-out points clamp into the padded range; OOB corners land in padding
    // slots the huber gather never reads.
    x0 = max(-2, min(128, x0));
    y0 = max(-2, min(128, y0));
    z0 = max(-2, min(128, z0));

    const float wx0 = 1.0f - fx, wx1 = fx;
    const float wy0 = 1.0f - fy, wy1 = fy;
    const float wz0 = (1.0f - fz) * sign, wz1 = fz * sign;

    const int sx = x0 & 1, sy = y0 & 1, sz = z0 & 1;
    const int bx = (x0 + sx + 2) >> 1;
    const int by = (y0 + sy + 2) >> 1;
    const int bz = (z0 + sz + 2) >> 1;
    const int rep = (sz << 2) | (sy << 1) | sx;

    uint4* addr = g_rep + (size_t)rep * BRICKS
                + ((size_t)bz * RB + by) * RB + bx;

    const float a00 = wx0 * wy0, a10 = wx1 * wy0;
    const float a01 = wx0 * wy1, a11 = wx1 * wy1;

    red_add_v4_bf16x2(addr,
        pack_bf16x2(a00 * wz0, a10 * wz0),
        pack_bf16x2(a01 * wz0, a11 * wz0),
        pack_bf16x2(a00 * wz1, a10 * wz1),
        pack_bf16x2(a01 * wz1, a11 * wz1));
}

__device__ __forceinline__ float4 ldcs4(const float4* p) {
    return __ldcs(p);
}

// ---------------------------------------------------------------------------
// Splat: 4 points per thread. Inputs read as 9 independent float4 streaming
// loads (evict-first, protects grid L2 residency). 8 reds per thread.
// ---------------------------------------------------------------------------
__global__ void splat_kernel(const float* __restrict__ pred,
                             const float* __restrict__ gt,
                             const float* __restrict__ coords,
                             int N, float* __restrict__ out) {
    const int t = blockIdx.x * blockDim.x + threadIdx.x;
    if (t == 0) *out = 0.f;          // huber accumulates into out
    const int p0 = t * 4;
    if (p0 >= N) return;

    if (p0 + 4 <= N) {
        const float4* c4 = (const float4*)(coords) + 3 * t;
        const float4* p4 = (const float4*)(pred)   + 3 * t;
        const float4* g4 = (const float4*)(gt)     + 3 * t;
        float co[12], pr[12], gv[12];
        float4 v;
        v = ldcs4(c4 + 0); co[0]=v.x; co[1]=v.y; co[2]=v.z; co[3]=v.w;
        v = ldcs4(c4 + 1); co[4]=v.x; co[5]=v.y; co[6]=v.z; co[7]=v.w;
        v = ldcs4(c4 + 2); co[8]=v.x; co[9]=v.y; co[10]=v.z; co[11]=v.w;
        v = ldcs4(p4 + 0); pr[0]=v.x; pr[1]=v.y; pr[2]=v.z; pr[3]=v.w;
        v = ldcs4(p4 + 1); pr[4]=v.x; pr[5]=v.y; pr[6]=v.z; pr[7]=v.w;
        v = ldcs4(p4 + 2); pr[8]=v.x; pr[9]=v.y; pr[10]=v.z; pr[11]=v.w;
        v = ldcs4(g4 + 0); gv[0]=v.x; gv[1]=v.y; gv[2]=v.z; gv[3]=v.w;
        v = ldcs4(g4 + 1); gv[4]=v.x; gv[5]=v.y; gv[6]=v.z; gv[7]=v.w;
        v = ldcs4(g4 + 2); gv[8]=v.x; gv[9]=v.y; gv[10]=v.z; gv[11]=v.w;

        #pragma unroll
        for (int i = 0; i < 4; ++i) {
            const float cx = co[3*i], cy = co[3*i+1], cz = co[3*i+2];
            splat_one(cx + pr[3*i], cy + pr[3*i+1], cz + pr[3*i+2],  1.0f);
            splat_one(cx + gv[3*i], cy + gv[3*i+1], cz + gv[3*i+2], -1.0f);
        }
    } else {
        for (int p = p0; p < N; ++p) {
            const float cx = coords[3*p], cy = coords[3*p+1], cz = coords[3*p+2];
            splat_one(cx + pred[3*p], cy + pred[3*p+1], cz + pred[3*p+2],  1.0f);
            splat_one(cx + gt[3*p],   cy + gt[3*p+1],   cz + gt[3*p+2],  -1.0f);
        }
    }
}

// ---------------------------------------------------------------------------
// Huber: 8 cells (one aligned x-octet) per thread. For each replica, the
// octet's 8 lanes live at one fixed 4-byte sub-offset of 4 (sx=0) or 5 (sx=1)
// CONSECUTIVE bricks -> 36 aligned bf16x2 loads per 8 cells, all independent.
// ---------------------------------------------------------------------------
#define HUB_THREADS 256
#define CELLS (GD * GD * GD)

__global__ void huber_kernel(float* __restrict__ out) {
    const unsigned* __restrict__ gu = reinterpret_cast<const unsigned*>(g_rep);
    const int t = blockIdx.x * HUB_THREADS + threadIdx.x;
    const int cell0 = t * 8;
    const int xx0 = cell0 & 127;            // even multiple of 8
    const int yy  = (cell0 >> 7) & 127;
    const int zz  = cell0 >> 14;
    const int B0  = (xx0 + 2) >> 1;

    float vc[8];
    #pragma unroll
    for (int j = 0; j < 8; ++j) vc[j] = 0.f;

    #pragma unroll
    for (int rep = 0; rep < 8; ++rep) {
        const int sx = rep & 1, sy = (rep >> 1) & 1, sz = rep >> 2;
        const int ly = (yy ^ sy) & 1;
        const int lz = (zz ^ sz) & 1;
        const int by = (yy - ly + sy + 2) >> 1;
        const int bz = (zz - lz + sz + 2) >> 1;
        const size_t brick0 = (size_t)rep * BRICKS
                            + ((size_t)bz * RB + by) * RB + B0;
        const int off = (lz << 1) | ly;     // uint within brick

        if (sx == 0) {
            unsigned u[4];
            #pragma unroll
            for (int k = 0; k < 4; ++k) u[k] = gu[(brick0 + k) * 4 + off];
            #pragma unroll
            for (int j = 0; j < 8; ++j) {
                const __nv_bfloat162 b2 =
                    *reinterpret_cast<const __nv_bfloat162*>(&u[j >> 1]);
                vc[j] += __bfloat162float((j & 1) ? b2.y : b2.x);
            }
        } else {
            unsigned u[5];
            #pragma unroll
            for (int k = 0; k < 5; ++k) u[k] = gu[(brick0 + k) * 4 + off];
            #pragma unroll
            for (int j = 0; j < 8; ++j) {
                // j even -> hi half of u[j/2]; j odd -> lo half of u[(j+1)/2]
                const int k = (j + 1) >> 1;
                const __nv_bfloat162 b2 =
                    *reinterpret_cast<const __nv_bfloat162*>(&u[k]);
                vc[j] += __bfloat162float((j & 1) ? b2.x : b2.y);
            }
        }
    }

    float s = 0.f;
    #pragma unroll
    for (int j = 0; j < 8; ++j) {
        const float a = fabsf(vc[j]);
        s += (a <= 1.f) ? 0.5f * vc[j] * vc[j] : a - 0.5f;
    }

    #pragma unroll
    for (int o = 16; o; o >>= 1) s += __shfl_xor_sync(0xFFFFFFFFu, s, o);

    __shared__ float smem[8];
    const int lane = threadIdx.x & 31;
    const int warp = threadIdx.x >> 5;
    if (lane == 0) smem[warp] = s;
    __syncthreads();

    if (warp == 0) {
        s = (lane < (HUB_THREADS >> 5)) ? smem[lane] : 0.f;
        #pragma unroll
        for (int o = 4; o; o >>= 1) s += __shfl_xor_sync(0xFFFFFFFFu, s, o);
        if (lane == 0) atomicAdd(out, s);
    }
}

// ---------------------------------------------------------------------------
// Zero the replica bricks (4 bricks = 64B per thread).
// ---------------------------------------------------------------------------
__global__ void zero_kernel() {
    const int i = (blockIdx.x * blockDim.x + threadIdx.x) * 4;
    if (i + 4 <= TOTAL_BRICKS) {
        const uint4 z = make_uint4(0u, 0u, 0u, 0u);
        g_rep[i] = z; g_rep[i+1] = z; g_rep[i+2] = z; g_rep[i+3] = z;
    } else {
        for (int k = i; k < TOTAL_BRICKS; ++k)
            g_rep[k] = make_uint4(0u, 0u, 0u, 0u);
    }
}

// ---------------------------------------------------------------------------
// Launch: splat -> huber -> zero
// ---------------------------------------------------------------------------
extern "C" void kernel_launch(void* const* d_in, const int* in_sizes, int n_in,
                              void* d_out, int out_size) {
    const float* pred   = (const float*)d_in[0];  // registration_pred [1,N,3]
    const float* gt     = (const float*)d_in[1];  // registration_gt   [1,N,3]
    const float* coords = (const float*)d_in[2];  // coords            [1,N,3]
    float* out = (float*)d_out;

    const int N = in_sizes[0] / 3;

    {   // splat: 4 points/thread (pred +1, gt -1); also zeroes *out
        const int threads = 256;
        const int nt = (N + 3) / 4;
        splat_kernel<<<(nt + threads - 1) / threads, threads>>>(
            pred, gt, coords, N, out);
    }
    {   // huber gather + reduction: 8 cells/thread
        const int nt = CELLS / 8;
        huber_kernel<<<nt / HUB_THREADS, HUB_THREADS>>>(out);
    }
    {   // reset replica bricks for next replay
        const int threads = 256;
        const int nt = (TOTAL_BRICKS + 3) / 4;
        zero_kernel<<<(nt + threads - 1) / threads, threads>>>();
    }
}

// round 6
// speedup vs baseline: 1.0074x; 1.0074x over previous
#include <cuda_runtime.h>
#include <cuda_bf16.h>

#define GD 128
#define RB 66                         // brick coords 0..65 cover x0 in [-2..128]
#define BRICKS (RB * RB * RB)         // 287,496 bricks per replica
#define TOTAL_BRICKS (8 * BRICKS)     // 8 parity replicas
// Each brick = 2x2x2 cells as bf16 = 16 bytes.
__device__ uint4 g_rep[TOTAL_BRICKS]; // 36.8 MB, zero-initialized at load;
                                      // zero_kernel restores invariant per call.

__device__ __forceinline__ unsigned pack_bf16x2(float lo, float hi) {
    unsigned u;
    asm("cvt.rn.bf16x2.f32 %0, %1, %2;" : "=r"(u) : "f"(hi), "f"(lo));
    return u;
}

__device__ __forceinline__ void red_add_v4_bf16x2(void* addr, unsigned a,
                                                  unsigned b, unsigned c,
                                                  unsigned d) {
    asm volatile("red.global.add.noftz.v4.bf16x2 [%0], {%1, %2, %3, %4};"
                 :: "l"(addr), "r"(a), "r"(b), "r"(c), "r"(d) : "memory");
}

// ---------------------------------------------------------------------------
// One splat = ONE v4.bf16x2 red: replica (x0&1,y0&1,z0&1) makes the 2x2x2
// corner cube one aligned 16B brick. Lane idx = lz*4 + ly*2 + lx.
// ---------------------------------------------------------------------------
__device__ __forceinline__ void splat_one(float cx, float cy, float cz,
                                          float sign) {
    const float x = fmaf(cx, 64.0f, 63.5f);   // ((c+1)*128-1)/2
    const float y = fmaf(cy, 64.0f, 63.5f);
    const float z = fmaf(cz, 64.0f, 63.5f);

    const float x0f = floorf(x), y0f = floorf(y), z0f = floorf(z);
    const float fx = x - x0f, fy = y - y0f, fz = z - z0f;
    int x0 = (int)x0f, y0 = (int)y0f, z0 = (int)z0f;
    // Far-out points clamp into the padded range; OOB corners land in padding
    // slots the huber gather never reads.
    x0 = max(-2, min(128, x0));
    y0 = max(-2, min(128, y0));
    z0 = max(-2, min(128, z0));

    const float wx0 = 1.0f - fx, wx1 = fx;
    const float wy0 = 1.0f - fy, wy1 = fy;
    const float wz0 = (1.0f - fz) * sign, wz1 = fz * sign;

    const int sx = x0 & 1, sy = y0 & 1, sz = z0 & 1;
    const int bx = (x0 + sx + 2) >> 1;
    const int by = (y0 + sy + 2) >> 1;
    const int bz = (z0 + sz + 2) >> 1;
    const int rep = (sz << 2) | (sy << 1) | sx;

    uint4* addr = g_rep + (size_t)rep * BRICKS
                + ((size_t)bz * RB + by) * RB + bx;

    const float a00 = wx0 * wy0, a10 = wx1 * wy0;
    const float a01 = wx0 * wy1, a11 = wx1 * wy1;

    red_add_v4_bf16x2(addr,
        pack_bf16x2(a00 * wz0, a10 * wz0),
        pack_bf16x2(a01 * wz0, a11 * wz0),
        pack_bf16x2(a00 * wz1, a10 * wz1),
        pack_bf16x2(a01 * wz1, a11 * wz1));
}

// ---------------------------------------------------------------------------
// Splat: ONE point per thread (occupancy >> 4-pt version), inputs via __ldcs
// (evict-first: don't let streamed inputs evict the L2-resident grid).
// ---------------------------------------------------------------------------
__global__ void splat_kernel(const float* __restrict__ pred,
                             const float* __restrict__ gt,
                             const float* __restrict__ coords,
                             int N, float* __restrict__ out) {
    const int p = blockIdx.x * blockDim.x + threadIdx.x;
    if (p == 0) *out = 0.f;      // huber (next kernel) accumulates into out
    if (p >= N) return;

    const float cx = __ldcs(coords + 3 * p + 0);
    const float cy = __ldcs(coords + 3 * p + 1);
    const float cz = __ldcs(coords + 3 * p + 2);
    const float px = __ldcs(pred + 3 * p + 0);
    const float py = __ldcs(pred + 3 * p + 1);
    const float pz = __ldcs(pred + 3 * p + 2);
    const float gx = __ldcs(gt + 3 * p + 0);
    const float gy = __ldcs(gt + 3 * p + 1);
    const float gz = __ldcs(gt + 3 * p + 2);

    splat_one(cx + px, cy + py, cz + pz,  1.0f);
    splat_one(cx + gx, cy + gy, cz + gz, -1.0f);
}

// ---------------------------------------------------------------------------
// Huber: 8 cells (one aligned x-octet) per thread. For each replica, the
// octet's 8 lanes live at one fixed 4-byte sub-offset of 4 (sx=0) or 5 (sx=1)
// CONSECUTIVE bricks -> 36 aligned bf16x2 loads per 8 cells, all independent.
// ---------------------------------------------------------------------------
#define HUB_THREADS 256
#define CELLS (GD * GD * GD)

__global__ void huber_kernel(float* __restrict__ out) {
    const unsigned* __restrict__ gu = reinterpret_cast<const unsigned*>(g_rep);
    const int t = blockIdx.x * HUB_THREADS + threadIdx.x;
    const int cell0 = t * 8;
    const int xx0 = cell0 & 127;            // even multiple of 8
    const int yy  = (cell0 >> 7) & 127;
    const int zz  = cell0 >> 14;
    const int B0  = (xx0 + 2) >> 1;

    float vc[8];
    #pragma unroll
    for (int j = 0; j < 8; ++j) vc[j] = 0.f;

    #pragma unroll
    for (int rep = 0; rep < 8; ++rep) {
        const int sx = rep & 1, sy = (rep >> 1) & 1, sz = rep >> 2;
        const int ly = (yy ^ sy) & 1;
        const int lz = (zz ^ sz) & 1;
        const int by = (yy - ly + sy + 2) >> 1;
        const int bz = (zz - lz + sz + 2) >> 1;
        const size_t brick0 = (size_t)rep * BRICKS
                            + ((size_t)bz * RB + by) * RB + B0;
        const int off = (lz << 1) | ly;     // uint within brick

        if (sx == 0) {
            unsigned u[4];
            #pragma unroll
            for (int k = 0; k < 4; ++k) u[k] = gu[(brick0 + k) * 4 + off];
            #pragma unroll
            for (int j = 0; j < 8; ++j) {
                const __nv_bfloat162 b2 =
                    *reinterpret_cast<const __nv_bfloat162*>(&u[j >> 1]);
                vc[j] += __bfloat162float((j & 1) ? b2.y : b2.x);
            }
        } else {
            unsigned u[5];
            #pragma unroll
            for (int k = 0; k < 5; ++k) u[k] = gu[(brick0 + k) * 4 + off];
            #pragma unroll
            for (int j = 0; j < 8; ++j) {
                // j even -> hi half of u[j/2]; j odd -> lo half of u[(j+1)/2]
                const int k = (j + 1) >> 1;
                const __nv_bfloat162 b2 =
                    *reinterpret_cast<const __nv_bfloat162*>(&u[k]);
                vc[j] += __bfloat162float((j & 1) ? b2.x : b2.y);
            }
        }
    }

    float s = 0.f;
    #pragma unroll
    for (int j = 0; j < 8; ++j) {
        const float a = fabsf(vc[j]);
        s += (a <= 1.f) ? 0.5f * vc[j] * vc[j] : a - 0.5f;
    }

    #pragma unroll
    for (int o = 16; o; o >>= 1) s += __shfl_xor_sync(0xFFFFFFFFu, s, o);

    __shared__ float smem[8];
    const int lane = threadIdx.x & 31;
    const int warp = threadIdx.x >> 5;
    if (lane == 0) smem[warp] = s;
    __syncthreads();

    if (warp == 0) {
        s = (lane < (HUB_THREADS >> 5)) ? smem[lane] : 0.f;
        #pragma unroll
        for (int o = 4; o; o >>= 1) s += __shfl_xor_sync(0xFFFFFFFFu, s, o);
        if (lane == 0) atomicAdd(out, s);
    }
}

// ---------------------------------------------------------------------------
// Zero the replica bricks (4 bricks = 64B per thread).
// ---------------------------------------------------------------------------
__global__ void zero_kernel() {
    const int i = (blockIdx.x * blockDim.x + threadIdx.x) * 4;
    if (i + 4 <= TOTAL_BRICKS) {
        const uint4 z = make_uint4(0u, 0u, 0u, 0u);
        g_rep[i] = z; g_rep[i+1] = z; g_rep[i+2] = z; g_rep[i+3] = z;
    } else {
        for (int k = i; k < TOTAL_BRICKS; ++k)
            g_rep[k] = make_uint4(0u, 0u, 0u, 0u);
    }
}

// ---------------------------------------------------------------------------
// Launch: splat -> huber -> zero
// ---------------------------------------------------------------------------
extern "C" void kernel_launch(void* const* d_in, const int* in_sizes, int n_in,
                              void* d_out, int out_size) {
    const float* pred   = (const float*)d_in[0];  // registration_pred [1,N,3]
    const float* gt     = (const float*)d_in[1];  // registration_gt   [1,N,3]
    const float* coords = (const float*)d_in[2];  // coords            [1,N,3]
    float* out = (float*)d_out;

    const int N = in_sizes[0] / 3;

    {   // splat: one thread per point (pred +1, gt -1); also zeroes *out
        const int threads = 256;
        splat_kernel<<<(N + threads - 1) / threads, threads>>>(
            pred, gt, coords, N, out);
    }
    {   // huber gather + reduction: 8 cells/thread
        const int nt = CELLS / 8;
        huber_kernel<<<nt / HUB_THREADS, HUB_THREADS>>>(out);
    }
    {   // reset replica bricks for next replay
        const int threads = 256;
        const int nt = (TOTAL_BRICKS + 3) / 4;
        zero_kernel<<<(nt + threads - 1) / threads, threads>>>();
    }
}